// round 9
// baseline (speedup 1.0000x reference)
#include <cuda_runtime.h>
#include <cuda_bf16.h>
#include <cuda_fp16.h>
#include <math.h>
#include <stdint.h>

// Problem constants
#define BB 16
#define TT 256
#define EE 256
#define HH 512
#define G4H 2048
#define VV 32000
#define MROWS 4096           // B*T, row r = t*16 + b
#define NCTA 128

// ------------------------- scratch (no mallocs allowed) -------------------------
__device__ float g_xw[(size_t)MROWS * G4H];       // xw1 = emb@W1+b1
__device__ __half g_h1rh[2][BB * HH];             // h1 ping-pong (fp16)
__device__ __half g_h2rh[2][BB * HH];             // h2 ping-pong (fp16)
__device__ __half g_ut[3 * (size_t)G4H * HH];     // U1^T|W2^T|U2^T fp16 [gc][k]
__device__ volatile int g_flags[NCTA];            // per-CTA step flags

// fp16 operands for the tensor-core dense layer
__device__ __half g_a_h[(size_t)MROWS * HH];      // written by LSTM layer-2 gates
__device__ __half g_b_h[(size_t)VV * HH];         // [v][h] transposed Wd

// ------------------------- small PTX helpers ------------------------------------
__device__ __forceinline__ uint32_t smem_u32(const void* p) {
    uint32_t a;
    asm("{ .reg .u64 t; cvta.to.shared.u64 t, %1; cvt.u32.u64 %0, t; }" : "=r"(a) : "l"(p));
    return a;
}
__device__ __forceinline__ void cp_async16(uint32_t saddr, const void* gptr) {
    asm volatile("cp.async.cg.shared.global [%0], [%1], 16;"
                 :: "r"(saddr), "l"(__cvta_generic_to_global(gptr)) : "memory");
}
__device__ __forceinline__ void cp_commit() {
    asm volatile("cp.async.commit_group;" ::: "memory");
}
template<int N>
__device__ __forceinline__ void cp_wait() {
    asm volatile("cp.async.wait_group %0;" :: "n"(N) : "memory");
}
__device__ __forceinline__ void ldm_x4(uint32_t* r, uint32_t a) {
    asm volatile("ldmatrix.sync.aligned.m8n8.x4.shared.b16 {%0,%1,%2,%3}, [%4];"
                 : "=r"(r[0]), "=r"(r[1]), "=r"(r[2]), "=r"(r[3]) : "r"(a));
}
__device__ __forceinline__ void mma_f16(float* d, const uint32_t* a, uint32_t b0, uint32_t b1) {
    asm volatile(
        "mma.sync.aligned.m16n8k16.row.col.f32.f16.f16.f32 "
        "{%0,%1,%2,%3}, {%4,%5,%6,%7}, {%8,%9}, {%0,%1,%2,%3};"
        : "+f"(d[0]), "+f"(d[1]), "+f"(d[2]), "+f"(d[3])
        : "r"(a[0]), "r"(a[1]), "r"(a[2]), "r"(a[3]), "r"(b0), "r"(b1));
}

// ------------------------- prep: sgemm0 + transB(Wd) + transU x3 ----------------
// blocks [0,512): xw1 GEMM tiles; [512,16512): Wd transpose; [16512,19584): U^T fp16
__global__ __launch_bounds__(256, 2)
void prep_kernel(const float* __restrict__ emb,
                 const float* __restrict__ W1,
                 const float* __restrict__ b1,
                 const int* __restrict__ tokens,
                 const float* __restrict__ Wd,
                 const float* __restrict__ U1,
                 const float* __restrict__ W2,
                 const float* __restrict__ U2)
{
    const int bid = blockIdx.x;
    const int tid = threadIdx.x;

    if (bid >= 16512) {
        // ---- transU role: U[512][2048] fp32 -> g_ut[mat][2048][512] fp16 ----
        __shared__ __half sh2[32][33];
        int tb = bid - 16512;
        int mat = tb >> 10;
        int t2 = tb & 1023;
        int k0 = (t2 & 15) * 32;
        int g0 = (t2 >> 4) * 32;
        const float* src = (mat == 0) ? U1 : (mat == 1) ? W2 : U2;
        int tx = tid & 31, ty = tid >> 5;
#pragma unroll
        for (int j = 0; j < 4; j++) {
            int kr = ty + j * 8;
            sh2[kr][tx] = __float2half(src[(size_t)(k0 + kr) * G4H + g0 + tx]);
        }
        __syncthreads();
#pragma unroll
        for (int j = 0; j < 4; j++) {
            int gr = ty + j * 8;
            g_ut[(size_t)mat * G4H * HH + (size_t)(g0 + gr) * HH + k0 + tx] = sh2[tx][gr];
        }
        return;
    }
    if (bid >= 512) {
        // ---- transB role: Wd[512][32000] -> g_b_h[32000][512] fp16 ----
        __shared__ __half sh[32][33];
        int tb = bid - 512;
        int v0 = (tb % 1000) * 32;
        int h0 = (tb / 1000) * 32;
        int tx = tid & 31, ty = tid >> 5;
#pragma unroll
        for (int j = 0; j < 4; j++) {
            int hr = ty + j * 8;
            sh[hr][tx] = __float2half(Wd[(size_t)(h0 + hr) * VV + v0 + tx]);
        }
        __syncthreads();
#pragma unroll
        for (int j = 0; j < 4; j++) {
            int vr = ty + j * 8;
            g_b_h[(size_t)(v0 + vr) * HH + h0 + tx] = sh[tx][vr];
        }
        return;
    }

    // ---- sgemm0 role (+ flag reset for the LSTM barrier, graph-replay safe) ----
    if (bid == 0 && tid < NCTA) g_flags[tid] = 0;

    const int K = EE, N = G4H;
    __shared__ float As[16][128];
    __shared__ float Bs[16][128];

    const int m0 = (bid >> 4) * 128;
    const int n0 = (bid & 15) * 128;
    const int rg = (tid >> 4) * 4;
    const int cg = (tid & 15) * 4;

    float acc[8][8];
#pragma unroll
    for (int i = 0; i < 8; i++)
#pragma unroll
        for (int j = 0; j < 8; j++) acc[i][j] = 0.f;

    for (int kt = 0; kt < K; kt += 16) {
        __syncthreads();
#pragma unroll
        for (int it = 0; it < 2; it++) {
            int item = tid + it * 256;
            int m = item >> 2;
            int kq = item & 3;
            int gr = m0 + m;
            int tok = tokens[((gr & 15) << 8) + (gr >> 4)];
            float4 v = *(const float4*)(emb + (size_t)tok * K + kt + kq * 4);
            As[kq * 4 + 0][m] = v.x;
            As[kq * 4 + 1][m] = v.y;
            As[kq * 4 + 2][m] = v.z;
            As[kq * 4 + 3][m] = v.w;
        }
#pragma unroll
        for (int it = 0; it < 2; it++) {
            int item = tid + it * 256;
            int k = item >> 5;
            int n4 = item & 31;
            float4 v = *(const float4*)(W1 + (size_t)(kt + k) * N + n0 + n4 * 4);
            *(float4*)&Bs[k][n4 * 4] = v;
        }
        __syncthreads();
#pragma unroll
        for (int kk = 0; kk < 16; kk++) {
            float4 a0 = *(const float4*)&As[kk][rg];
            float4 a1 = *(const float4*)&As[kk][64 + rg];
            float4 b0 = *(const float4*)&Bs[kk][cg];
            float4 b1 = *(const float4*)&Bs[kk][64 + cg];
            float a[8] = {a0.x, a0.y, a0.z, a0.w, a1.x, a1.y, a1.z, a1.w};
            float b[8] = {b0.x, b0.y, b0.z, b0.w, b1.x, b1.y, b1.z, b1.w};
#pragma unroll
            for (int i = 0; i < 8; i++)
#pragma unroll
                for (int j = 0; j < 8; j++)
                    acc[i][j] += a[i] * b[j];
        }
    }

    float bj[8];
#pragma unroll
    for (int j = 0; j < 4; j++) {
        bj[j]     = b1[n0 + cg + j];
        bj[4 + j] = b1[n0 + 64 + cg + j];
    }
#pragma unroll
    for (int i = 0; i < 8; i++) {
        int r = m0 + ((i < 4) ? (rg + i) : (64 + rg + i - 4));
        float4 o0, o1;
        o0.x = acc[i][0] + bj[0]; o0.y = acc[i][1] + bj[1];
        o0.z = acc[i][2] + bj[2]; o0.w = acc[i][3] + bj[3];
        o1.x = acc[i][4] + bj[4]; o1.y = acc[i][5] + bj[5];
        o1.z = acc[i][6] + bj[6]; o1.w = acc[i][7] + bj[7];
        *(float4*)&g_xw[(size_t)r * N + n0 + cg]      = o0;
        *(float4*)&g_xw[(size_t)r * N + n0 + 64 + cg] = o1;
    }
}

// ------------------------- fused dual-layer LSTM on tensor cores ----------------
// 128 CTAs x 256 threads (8 warps), persistent. CTA owns 4 hidden units for BOTH
// layers. Step s: h1[s] (s<256) and h2[s-1] (s>=1). 12 TC jobs per step.
// Barrier = distributed per-CTA flags (parallel stores + vectorized polling),
// NOT a contended atomic counter.
#define LSTM_SMEM 98048
__global__ __launch_bounds__(256, 1)
void lstm_tc_kernel(const float* __restrict__ b2)
{
    extern __shared__ char lsm[];
    char* Bsl = lsm;                       // 3*16*1040
    char* h1st = lsm + 49920;              // 16*1040
    char* h2st = lsm + 66560;              // 16*1040
    float* zp = (float*)(lsm + 83200);     // [12][16][16]
    float* zsh1 = (float*)(lsm + 95488);   // [256]
    float* zsh2 = (float*)(lsm + 96512);   // [256]
    float* cs = (float*)(lsm + 97536);     // c1[64] c2[64]

    const int tid = threadIdx.x;
    const int wid = tid >> 5;
    const int lane = tid & 31;
    const int ct = blockIdx.x;
    const int hu0 = ct * 4;
    const uint32_t Bsl_a = smem_u32(Bsl);
    const uint32_t h1_a = smem_u32(h1st);
    const uint32_t h2_a = smem_u32(h2st);

    // ---- init: load B slices (g_ut rows are coalesced 1KB) ----
    for (int i = tid; i < 3072; i += 256) {
        int mat = i >> 10;
        int rem = i & 1023;
        int n = rem >> 6;
        int ch = rem & 63;
        int gc = (n >> 2) * HH + hu0 + (n & 3);
        cp_async16(Bsl_a + (uint32_t)(mat * 16640 + n * 1040 + ch * 16),
                   g_ut + (size_t)mat * G4H * HH + (size_t)gc * HH + ch * 8);
    }
    cp_commit();
    // zero h stages (2 x 16640 B contiguous)
    for (int i = tid; i < 2080; i += 256)
        *(uint4*)(h1st + i * 16) = make_uint4(0, 0, 0, 0);
    if (tid < 128) cs[tid] = 0.f;
    cp_wait<0>();
    __syncthreads();

    // reduce-role constants: thread = (b = tid/16, n = tid%16)
    const int rb = tid >> 4;
    const int rn = tid & 15;
    const int rgc = (rn >> 2) * HH + hu0 + (rn & 3);
    const float b2v = __ldg(b2 + rgc);

    const uint32_t lrow = (uint32_t)(lane & 15) * 1040u;
    const uint32_t lsel = (uint32_t)((lane >> 4) << 4);

    for (int s = 0; s <= TT; s++) {
        // ---- stage h1[s-1], h2[s-2] as fp16 (1024 chunks each) ----
        if (s >= 1) {
            const __half* hp = g_h1rh[(s - 1) & 1];
#pragma unroll
            for (int i = 0; i < 4; i++) {
                int u = tid + i * 256;        // 0..1023
                int b = u >> 6, ch = u & 63;
                cp_async16(h1_a + (uint32_t)(b * 1040 + ch * 16), hp + b * HH + ch * 8);
            }
            if (s >= 2) {
                const __half* hq = g_h2rh[s & 1];
#pragma unroll
                for (int i = 0; i < 4; i++) {
                    int u = tid + i * 256;
                    int b = u >> 6, ch = u & 63;
                    cp_async16(h2_a + (uint32_t)(b * 1040 + ch * 16), hq + b * HH + ch * 8);
                }
            }
            cp_commit();
            cp_wait<0>();
        }
        __syncthreads();

        // ---- tensor-core matvecs: up to 2 jobs per warp ----
#pragma unroll
        for (int jj = 0; jj < 2; jj++) {
            int j = wid + jj * 8;
            if (j < 12) {
                int mat = j >> 2, ksl = j & 3;
                uint32_t Ab = ((mat == 2) ? h2_a : h1_a) + (uint32_t)(ksl * 256) + lrow + lsel;
                uint32_t Bb = Bsl_a + (uint32_t)(mat * 16640 + ksl * 256) + lrow + lsel;
                float acc[2][4] = {{0.f, 0.f, 0.f, 0.f}, {0.f, 0.f, 0.f, 0.f}};
#pragma unroll
                for (int c = 0; c < 8; c++) {
                    uint32_t a[4], bf[4];
                    ldm_x4(a, Ab + (uint32_t)(c * 32));
                    ldm_x4(bf, Bb + (uint32_t)(c * 32));
                    mma_f16(acc[0], a, bf[0], bf[2]);
                    mma_f16(acc[1], a, bf[1], bf[3]);
                }
                int r0 = lane >> 2, c0 = (lane & 3) * 2;
                float* zj = zp + j * 256;
#pragma unroll
                for (int nt = 0; nt < 2; nt++) {
                    zj[r0 * 16 + nt * 8 + c0]           = acc[nt][0];
                    zj[r0 * 16 + nt * 8 + c0 + 1]       = acc[nt][1];
                    zj[(r0 + 8) * 16 + nt * 8 + c0]     = acc[nt][2];
                    zj[(r0 + 8) * 16 + nt * 8 + c0 + 1] = acc[nt][3];
                }
            }
        }
        __syncthreads();

        // ---- reduce over 4 k-slices ----
        {
            float z1 = (s < TT) ? __ldg(&g_xw[((size_t)s * BB + rb) * G4H + rgc]) : 0.f;
            float z2 = b2v;
            int o = rb * 16 + rn;
#pragma unroll
            for (int ksl = 0; ksl < 4; ksl++) {
                z1 += zp[ksl * 256 + o];
                z2 += zp[(4 + ksl) * 256 + o] + zp[(8 + ksl) * 256 + o];
            }
            zsh1[o] = z1;
            zsh2[o] = z2;
        }
        __syncthreads();

        // ---- gates: tid<64 layer1, 64..127 layer2 ----
        if (tid < 64) {
            if (s < TT) {
                int b = tid >> 2, u = tid & 3;
                float zi = zsh1[b * 16 + u];
                float zf = zsh1[b * 16 + 4 + u];
                float zg = zsh1[b * 16 + 8 + u];
                float zo = zsh1[b * 16 + 12 + u];
                float ig = 1.f / (1.f + expf(-zi));
                float fg = 1.f / (1.f + expf(-zf));
                float gg = tanhf(zg);
                float og = 1.f / (1.f + expf(-zo));
                float c = fg * cs[tid] + ig * gg;
                cs[tid] = c;
                g_h1rh[s & 1][b * HH + hu0 + u] = __float2half(og * tanhf(c));
                __threadfence();
            }
        } else if (tid < 128) {
            if (s >= 1) {
                int w = tid - 64;
                int b = w >> 2, u = w & 3;
                int t = s - 1;
                float zi = zsh2[b * 16 + u];
                float zf = zsh2[b * 16 + 4 + u];
                float zg = zsh2[b * 16 + 8 + u];
                float zo = zsh2[b * 16 + 12 + u];
                float ig = 1.f / (1.f + expf(-zi));
                float fg = 1.f / (1.f + expf(-zf));
                float gg = tanhf(zg);
                float og = 1.f / (1.f + expf(-zo));
                float c = fg * cs[tid] + ig * gg;
                cs[tid] = c;
                float h = og * tanhf(c);
                __half hh = __float2half(h);
                g_h2rh[t & 1][b * HH + hu0 + u] = hh;
                g_a_h[((size_t)t * BB + b) * HH + hu0 + u] = hh;
                __threadfence();
            }
        }

        // ---- distributed flag barrier: parallel stores, vectorized polling ----
        __syncthreads();
        if (tid < 32) {
            if (tid == 0) g_flags[ct] = s + 1;
            const int tgt = s + 1;
            bool ok;
            do {
                int m0 = g_flags[lane];
                int m1 = g_flags[lane + 32];
                int m2 = g_flags[lane + 64];
                int m3 = g_flags[lane + 96];
                int m = min(min(m0, m1), min(m2, m3));
                ok = __all_sync(0xffffffffu, m >= tgt);
            } while (!ok);
            __threadfence();
        }
        __syncthreads();
    }
}

// ------------------------- HMMA dense GEMM (fp16, 3-stage pipeline) -------------
#define DARR 10240u          // bytes per sub-array (128*80)
#define DSTG 20480u          // bytes per stage (A|B)

__device__ __forceinline__ void dense_load_chunk(uint32_t sb, int m0, int n0, int c, int tid)
{
    const uint32_t stg = sb + (uint32_t)(c % 3) * DSTG;
    const int kc0 = c * 32;
#pragma unroll
    for (int it = 0; it < 4; it++) {
        int u = tid + it * 256;          // 0..1023 16B units
        int arr = u >> 9;                // 0 A, 1 B
        int u2 = u & 511;
        int r = u2 >> 2, q = u2 & 3;
        const __half* g = arr ? g_b_h : g_a_h;
        int grow = arr ? n0 : m0;
        cp_async16(stg + (uint32_t)arr * DARR + (uint32_t)(r * 80 + q * 16),
                   g + (size_t)(grow + r) * HH + kc0 + q * 8);
    }
    cp_commit();
}

__global__ __launch_bounds__(256, 2)
void dense_kernel(const float* __restrict__ bd, float* __restrict__ out)
{
    extern __shared__ char smem[];
    const uint32_t sb = smem_u32(smem);
    const int tid = threadIdx.x;
    const int wid = tid >> 5;
    const int lane = tid & 31;
    const int n0 = blockIdx.x * 128;
    const int m0 = blockIdx.y * 128;
    const int wm = wid & 1;
    const int wn = wid >> 1;
    const int lrow = lane & 15;
    const int lsel = (lane >> 4) << 4;

    float acc[4][4][4];
#pragma unroll
    for (int mt = 0; mt < 4; mt++)
#pragma unroll
        for (int nt = 0; nt < 4; nt++)
#pragma unroll
            for (int e = 0; e < 4; e++) acc[mt][nt][e] = 0.f;

    dense_load_chunk(sb, m0, n0, 0, tid);
    dense_load_chunk(sb, m0, n0, 1, tid);

    for (int c = 0; c < 16; c++) {
        if (c < 15) cp_wait<1>(); else cp_wait<0>();
        __syncthreads();
        if (c + 2 < 16) dense_load_chunk(sb, m0, n0, c + 2, tid);

        const uint32_t stg = sb + (uint32_t)(c % 3) * DSTG;
        const uint32_t a_b = stg + (uint32_t)((wm * 64 + lrow) * 80) + lsel;
        const uint32_t b_b = stg + DARR + (uint32_t)((wn * 32 + lrow) * 80) + lsel;
#pragma unroll
        for (int s = 0; s < 2; s++) {
            uint32_t bf[2][4];
#pragma unroll
            for (int i = 0; i < 2; i++)
                ldm_x4(bf[i], b_b + (uint32_t)(i * 16 * 80 + s * 32));
#pragma unroll
            for (int mt = 0; mt < 4; mt++) {
                uint32_t a[4];
                ldm_x4(a, a_b + (uint32_t)(mt * 16 * 80 + s * 32));
#pragma unroll
                for (int nt = 0; nt < 4; nt++) {
                    uint32_t b0 = bf[nt >> 1][nt & 1];
                    uint32_t b1 = bf[nt >> 1][(nt & 1) + 2];
                    mma_f16(acc[mt][nt], a, b0, b1);
                }
            }
        }
    }

    // epilogue: direct stores with [t*16+b] -> [b*256+t] row remap
    const int g = lane >> 2;
    const int tig = lane & 3;
#pragma unroll
    for (int nt = 0; nt < 4; nt++) {
        int col = n0 + wn * 32 + nt * 8 + tig * 2;
        float b0 = __ldg(bd + col);
        float b1 = __ldg(bd + col + 1);
#pragma unroll
        for (int mt = 0; mt < 4; mt++) {
            int r0 = m0 + wm * 64 + mt * 16 + g;
            int r1 = r0 + 8;
            size_t o0 = (size_t)((r0 & 15) * 256 + (r0 >> 4));
            size_t o1 = (size_t)((r1 & 15) * 256 + (r1 >> 4));
            float2 v0 = make_float2(acc[mt][nt][0] + b0, acc[mt][nt][1] + b1);
            float2 v1 = make_float2(acc[mt][nt][2] + b0, acc[mt][nt][3] + b1);
            *(float2*)(out + o0 * VV + col) = v0;
            *(float2*)(out + o1 * VV + col) = v1;
        }
    }
}

// ------------------------- launch -----------------------------------------------
extern "C" void kernel_launch(void* const* d_in, const int* in_sizes, int n_in,
                              void* d_out, int out_size)
{
    const int*   tokens = (const int*)  d_in[0];
    const float* emb    = (const float*)d_in[1];
    const float* W1     = (const float*)d_in[2];
    const float* U1     = (const float*)d_in[3];
    const float* b1     = (const float*)d_in[4];
    const float* W2     = (const float*)d_in[5];
    const float* U2     = (const float*)d_in[6];
    const float* b2     = (const float*)d_in[7];
    const float* Wd     = (const float*)d_in[8];
    const float* bd     = (const float*)d_in[9];
    float* out = (float*)d_out;

    cudaFuncSetAttribute(dense_kernel, cudaFuncAttributeMaxDynamicSharedMemorySize,
                         (int)(3 * DSTG));
    cudaFuncSetAttribute(lstm_tc_kernel, cudaFuncAttributeMaxDynamicSharedMemorySize,
                         LSTM_SMEM);

    // 1) fused prep: xw1 GEMM (+flag reset) + Wd transpose + U^T fp16
    prep_kernel<<<512 + 16000 + 3072, 256>>>(emb, W1, b1, tokens, Wd, U1, W2, U2);
    // 2) fused dual-layer LSTM on tensor cores; layer 2 writes fp16 g_a_h
    lstm_tc_kernel<<<NCTA, 256, LSTM_SMEM>>>(b2);
    // 3) logits = h2 @ Wd + bd on HMMA tensor cores (fp16 single pass)
    dense_kernel<<<dim3(VV / 128, MROWS / 128), 256, 3 * DSTG>>>(bd, out);
}

// round 10
// speedup vs baseline: 2.0252x; 2.0252x over previous
#include <cuda_runtime.h>
#include <cuda_bf16.h>
#include <cuda_fp16.h>
#include <math.h>
#include <stdint.h>

// Problem constants
#define BB 16
#define TT 256
#define EE 256
#define HH 512
#define G4H 2048
#define VV 32000
#define MROWS 4096           // B*T, row r = t*16 + b
#define NCTA 64              // LSTM CTA count (8 hidden units each)

// ------------------------- scratch (no mallocs allowed) -------------------------
__device__ float g_xw[(size_t)MROWS * G4H];       // xw1 = emb@W1+b1
__device__ __half g_h1rh[2][BB * HH];             // h1 ping-pong (fp16)
__device__ __half g_h2rh[2][BB * HH];             // h2 ping-pong (fp16)
__device__ __half g_ut[3 * (size_t)G4H * HH];     // U1^T|W2^T|U2^T fp16 [gc][k]
__device__ unsigned g_bar_count;
__device__ unsigned g_bar_gen;

// fp16 operands for the tensor-core dense layer
__device__ __half g_a_h[(size_t)MROWS * HH];      // written by LSTM layer-2 gates
__device__ __half g_b_h[(size_t)VV * HH];         // [v][h] transposed Wd

// ------------------------- small PTX helpers ------------------------------------
__device__ __forceinline__ uint32_t smem_u32(const void* p) {
    uint32_t a;
    asm("{ .reg .u64 t; cvta.to.shared.u64 t, %1; cvt.u32.u64 %0, t; }" : "=r"(a) : "l"(p));
    return a;
}
__device__ __forceinline__ void cp_async16(uint32_t saddr, const void* gptr) {
    asm volatile("cp.async.cg.shared.global [%0], [%1], 16;"
                 :: "r"(saddr), "l"(__cvta_generic_to_global(gptr)) : "memory");
}
__device__ __forceinline__ void cp_commit() {
    asm volatile("cp.async.commit_group;" ::: "memory");
}
template<int N>
__device__ __forceinline__ void cp_wait() {
    asm volatile("cp.async.wait_group %0;" :: "n"(N) : "memory");
}
__device__ __forceinline__ void ldm_x4(uint32_t* r, uint32_t a) {
    asm volatile("ldmatrix.sync.aligned.m8n8.x4.shared.b16 {%0,%1,%2,%3}, [%4];"
                 : "=r"(r[0]), "=r"(r[1]), "=r"(r[2]), "=r"(r[3]) : "r"(a));
}
__device__ __forceinline__ void mma_f16(float* d, const uint32_t* a, uint32_t b0, uint32_t b1) {
    asm volatile(
        "mma.sync.aligned.m16n8k16.row.col.f32.f16.f16.f32 "
        "{%0,%1,%2,%3}, {%4,%5,%6,%7}, {%8,%9}, {%0,%1,%2,%3};"
        : "+f"(d[0]), "+f"(d[1]), "+f"(d[2]), "+f"(d[3])
        : "r"(a[0]), "r"(a[1]), "r"(a[2]), "r"(a[3]), "r"(b0), "r"(b1));
}

// ------------------------- global barrier (all CTAs resident) -------------------
__device__ __forceinline__ void grid_barrier(int ncta) {
    __syncthreads();
    if (threadIdx.x == 0) {
        __threadfence();
        unsigned gen = *(volatile unsigned*)&g_bar_gen;
        if (atomicAdd(&g_bar_count, 1u) == (unsigned)(ncta - 1)) {
            g_bar_count = 0;
            __threadfence();
            *(volatile unsigned*)&g_bar_gen = gen + 1u;
        } else {
            while (*(volatile unsigned*)&g_bar_gen == gen) { }
            __threadfence();
        }
    }
    __syncthreads();
}

// ------------------------- prep: sgemm0 + transB(Wd) + transU x3 ----------------
// blocks [0,512): xw1 GEMM tiles; [512,16512): Wd transpose; [16512,19584): U^T fp16
__global__ __launch_bounds__(256, 2)
void prep_kernel(const float* __restrict__ emb,
                 const float* __restrict__ W1,
                 const float* __restrict__ b1,
                 const int* __restrict__ tokens,
                 const float* __restrict__ Wd,
                 const float* __restrict__ U1,
                 const float* __restrict__ W2,
                 const float* __restrict__ U2)
{
    const int bid = blockIdx.x;
    const int tid = threadIdx.x;

    if (bid >= 16512) {
        // ---- transU role: U[512][2048] fp32 -> g_ut[mat][2048][512] fp16 ----
        __shared__ __half sh2[32][33];
        int tb = bid - 16512;
        int mat = tb >> 10;
        int t2 = tb & 1023;
        int k0 = (t2 & 15) * 32;
        int g0 = (t2 >> 4) * 32;
        const float* src = (mat == 0) ? U1 : (mat == 1) ? W2 : U2;
        int tx = tid & 31, ty = tid >> 5;
#pragma unroll
        for (int j = 0; j < 4; j++) {
            int kr = ty + j * 8;
            sh2[kr][tx] = __float2half(src[(size_t)(k0 + kr) * G4H + g0 + tx]);
        }
        __syncthreads();
#pragma unroll
        for (int j = 0; j < 4; j++) {
            int gr = ty + j * 8;
            g_ut[(size_t)mat * G4H * HH + (size_t)(g0 + gr) * HH + k0 + tx] = sh2[tx][gr];
        }
        return;
    }
    if (bid >= 512) {
        // ---- transB role: Wd[512][32000] -> g_b_h[32000][512] fp16 ----
        __shared__ __half sh[32][33];
        int tb = bid - 512;
        int v0 = (tb % 1000) * 32;
        int h0 = (tb / 1000) * 32;
        int tx = tid & 31, ty = tid >> 5;
#pragma unroll
        for (int j = 0; j < 4; j++) {
            int hr = ty + j * 8;
            sh[hr][tx] = __float2half(Wd[(size_t)(h0 + hr) * VV + v0 + tx]);
        }
        __syncthreads();
#pragma unroll
        for (int j = 0; j < 4; j++) {
            int vr = ty + j * 8;
            g_b_h[(size_t)(v0 + vr) * HH + h0 + tx] = sh[tx][vr];
        }
        return;
    }

    // ---- sgemm0 role ----
    const int K = EE, N = G4H;
    __shared__ float As[16][128];
    __shared__ float Bs[16][128];

    const int m0 = (bid >> 4) * 128;
    const int n0 = (bid & 15) * 128;
    const int rg = (tid >> 4) * 4;
    const int cg = (tid & 15) * 4;

    float acc[8][8];
#pragma unroll
    for (int i = 0; i < 8; i++)
#pragma unroll
        for (int j = 0; j < 8; j++) acc[i][j] = 0.f;

    for (int kt = 0; kt < K; kt += 16) {
        __syncthreads();
#pragma unroll
        for (int it = 0; it < 2; it++) {
            int item = tid + it * 256;
            int m = item >> 2;
            int kq = item & 3;
            int gr = m0 + m;
            int tok = tokens[((gr & 15) << 8) + (gr >> 4)];
            float4 v = *(const float4*)(emb + (size_t)tok * K + kt + kq * 4);
            As[kq * 4 + 0][m] = v.x;
            As[kq * 4 + 1][m] = v.y;
            As[kq * 4 + 2][m] = v.z;
            As[kq * 4 + 3][m] = v.w;
        }
#pragma unroll
        for (int it = 0; it < 2; it++) {
            int item = tid + it * 256;
            int k = item >> 5;
            int n4 = item & 31;
            float4 v = *(const float4*)(W1 + (size_t)(kt + k) * N + n0 + n4 * 4);
            *(float4*)&Bs[k][n4 * 4] = v;
        }
        __syncthreads();
#pragma unroll
        for (int kk = 0; kk < 16; kk++) {
            float4 a0 = *(const float4*)&As[kk][rg];
            float4 a1 = *(const float4*)&As[kk][64 + rg];
            float4 b0 = *(const float4*)&Bs[kk][cg];
            float4 b1 = *(const float4*)&Bs[kk][64 + cg];
            float a[8] = {a0.x, a0.y, a0.z, a0.w, a1.x, a1.y, a1.z, a1.w};
            float b[8] = {b0.x, b0.y, b0.z, b0.w, b1.x, b1.y, b1.z, b1.w};
#pragma unroll
            for (int i = 0; i < 8; i++)
#pragma unroll
                for (int j = 0; j < 8; j++)
                    acc[i][j] += a[i] * b[j];
        }
    }

    float bj[8];
#pragma unroll
    for (int j = 0; j < 4; j++) {
        bj[j]     = b1[n0 + cg + j];
        bj[4 + j] = b1[n0 + 64 + cg + j];
    }
#pragma unroll
    for (int i = 0; i < 8; i++) {
        int r = m0 + ((i < 4) ? (rg + i) : (64 + rg + i - 4));
        float4 o0, o1;
        o0.x = acc[i][0] + bj[0]; o0.y = acc[i][1] + bj[1];
        o0.z = acc[i][2] + bj[2]; o0.w = acc[i][3] + bj[3];
        o1.x = acc[i][4] + bj[4]; o1.y = acc[i][5] + bj[5];
        o1.z = acc[i][6] + bj[6]; o1.w = acc[i][7] + bj[7];
        *(float4*)&g_xw[(size_t)r * N + n0 + cg]      = o0;
        *(float4*)&g_xw[(size_t)r * N + n0 + 64 + cg] = o1;
    }
}

// ------------------------- fused dual-layer LSTM on tensor cores ----------------
// 64 CTAs x 512 threads (16 warps), persistent. CTA owns 8 hidden units for BOTH
// layers (32 gate cols per matrix). Step s: h1[s] (s<256), h2[s-1] (s>=1).
// 24 TC jobs = {U1,W2,U2} x {ntile 0,1} x {4 k-slices}; warp w does j = w, w+16.
// Wait — 16 warps x {w, w+8? }  jobs j = w + 16*jj for jj in {0} plus j=w+? :
// 24 jobs over 16 warps: warp w does j=w and (w<8 ? j=16+w : none).
// Barrier participants halved vs R8 (64 atomic arrivals, 63 pollers).
// SMEM bytes:
//   Bsl    0       3*32*1040 = 99840
//   h1st   99840   16*1040   = 16640
//   h2st   116480  16*1040   = 16640
//   zp     133120  24*256*4  = 24576
//   zsh1   157696  512*4     = 2048
//   zsh2   159744  512*4     = 2048
//   cs     161792  256*4     = 1024   -> total 162816
#define LSTM_SMEM 162816
__global__ __launch_bounds__(512, 1)
void lstm_tc_kernel(const float* __restrict__ b2)
{
    extern __shared__ char lsm[];
    char* Bsl = lsm;
    char* h1st = lsm + 99840;
    char* h2st = lsm + 116480;
    float* zp = (float*)(lsm + 133120);
    float* zsh1 = (float*)(lsm + 157696);
    float* zsh2 = (float*)(lsm + 159744);
    float* cs = (float*)(lsm + 161792);

    const int tid = threadIdx.x;
    const int wid = tid >> 5;
    const int lane = tid & 31;
    const int ct = blockIdx.x;
    const int hu0 = ct * 8;
    const uint32_t Bsl_a = smem_u32(Bsl);
    const uint32_t h1_a = smem_u32(h1st);
    const uint32_t h2_a = smem_u32(h2st);

    // ---- init: load B slices (g_ut rows are coalesced 1KB) ----
    for (int i = tid; i < 6144; i += 512) {
        int mat = i >> 11;
        int rem = i & 2047;
        int n = rem >> 6;                 // 0..31 gate col idx (g*8+u)
        int ch = rem & 63;
        int gc = (n >> 3) * HH + hu0 + (n & 7);
        cp_async16(Bsl_a + (uint32_t)(mat * 33280 + n * 1040 + ch * 16),
                   g_ut + (size_t)mat * G4H * HH + (size_t)gc * HH + ch * 8);
    }
    cp_commit();
    // zero h stages (2 x 16640 B contiguous at h1st)
    for (int i = tid; i < 2080; i += 512)
        *(uint4*)(h1st + i * 16) = make_uint4(0, 0, 0, 0);
    if (tid < 256) cs[tid] = 0.f;
    cp_wait<0>();
    __syncthreads();

    // reduce-role constants: thread -> (b = tid/32, n = tid%32)
    const int rb = tid >> 5;
    const int rn = tid & 31;
    const int rgc = (rn >> 3) * HH + hu0 + (rn & 7);
    const float b2v = __ldg(b2 + rgc);

    const uint32_t lrow = (uint32_t)(lane & 15) * 1040u;
    const uint32_t lsel = (uint32_t)((lane >> 4) << 4);

    for (int s = 0; s <= TT; s++) {
        // prefetch xw operand early (consumed in reduce, after two syncs)
        float xwv = (s < TT) ? __ldg(&g_xw[((size_t)s * BB + rb) * G4H + rgc]) : 0.f;

        // ---- stage h1[s-1], h2[s-2] as fp16 (1024 chunks each) ----
        if (s >= 1) {
            const __half* hp = g_h1rh[(s - 1) & 1];
#pragma unroll
            for (int i = 0; i < 2; i++) {
                int u = tid + i * 512;        // 0..1023
                int b = u >> 6, ch = u & 63;
                cp_async16(h1_a + (uint32_t)(b * 1040 + ch * 16), hp + b * HH + ch * 8);
            }
            if (s >= 2) {
                const __half* hq = g_h2rh[s & 1];
#pragma unroll
                for (int i = 0; i < 2; i++) {
                    int u = tid + i * 512;
                    int b = u >> 6, ch = u & 63;
                    cp_async16(h2_a + (uint32_t)(b * 1040 + ch * 16), hq + b * HH + ch * 8);
                }
            }
            cp_commit();
            cp_wait<0>();
        }
        __syncthreads();

        // ---- tensor-core matvecs: job j = (mat, ntile, ksl) ----
#pragma unroll
        for (int jj = 0; jj < 2; jj++) {
            int j = (jj == 0) ? wid : (16 + wid);
            if (j < 24) {
                int mat = j >> 3;
                int rem = j & 7;
                int ntile = rem >> 2;
                int ksl = rem & 3;
                uint32_t Ab = ((mat == 2) ? h2_a : h1_a) + (uint32_t)(ksl * 256) + lrow + lsel;
                uint32_t Bb = Bsl_a + (uint32_t)(mat * 33280 + ntile * 16 * 1040 + ksl * 256)
                              + lrow + lsel;
                float acc[2][4] = {{0.f, 0.f, 0.f, 0.f}, {0.f, 0.f, 0.f, 0.f}};
#pragma unroll
                for (int c = 0; c < 8; c++) {
                    uint32_t a[4], bf[4];
                    ldm_x4(a, Ab + (uint32_t)(c * 32));
                    ldm_x4(bf, Bb + (uint32_t)(c * 32));
                    mma_f16(acc[0], a, bf[0], bf[2]);
                    mma_f16(acc[1], a, bf[1], bf[3]);
                }
                int r0 = lane >> 2, c0 = (lane & 3) * 2;
                float* zj = zp + j * 256;
#pragma unroll
                for (int nt = 0; nt < 2; nt++) {
                    zj[r0 * 16 + nt * 8 + c0]           = acc[nt][0];
                    zj[r0 * 16 + nt * 8 + c0 + 1]       = acc[nt][1];
                    zj[(r0 + 8) * 16 + nt * 8 + c0]     = acc[nt][2];
                    zj[(r0 + 8) * 16 + nt * 8 + c0 + 1] = acc[nt][3];
                }
            }
        }
        __syncthreads();

        // ---- reduce over 4 k-slices: thread (rb, rn) ----
        {
            int ntile = rn >> 4;
            int o16 = rb * 16 + (rn & 15);
            float z1 = xwv, z2 = b2v;
#pragma unroll
            for (int ksl = 0; ksl < 4; ksl++) {
                z1 += zp[(ntile * 4 + ksl) * 256 + o16];
                z2 += zp[(8 + ntile * 4 + ksl) * 256 + o16]
                    + zp[(16 + ntile * 4 + ksl) * 256 + o16];
            }
            zsh1[rb * 32 + rn] = z1;
            zsh2[rb * 32 + rn] = z2;
        }
        __syncthreads();

        // ---- gates: tid<128 layer1, 128..255 layer2 (16 b x 8 u each) ----
        if (tid < 128) {
            if (s < TT) {
                int b = tid >> 3, u = tid & 7;
                float zi = zsh1[b * 32 + u];
                float zf = zsh1[b * 32 + 8 + u];
                float zg = zsh1[b * 32 + 16 + u];
                float zo = zsh1[b * 32 + 24 + u];
                float ig = 1.f / (1.f + expf(-zi));
                float fg = 1.f / (1.f + expf(-zf));
                float gg = tanhf(zg);
                float og = 1.f / (1.f + expf(-zo));
                float c = fg * cs[tid] + ig * gg;
                cs[tid] = c;
                g_h1rh[s & 1][b * HH + hu0 + u] = __float2half(og * tanhf(c));
                __threadfence();
            }
        } else if (tid < 256) {
            if (s >= 1) {
                int w = tid - 128;
                int b = w >> 3, u = w & 7;
                int t = s - 1;
                float zi = zsh2[b * 32 + u];
                float zf = zsh2[b * 32 + 8 + u];
                float zg = zsh2[b * 32 + 16 + u];
                float zo = zsh2[b * 32 + 24 + u];
                float ig = 1.f / (1.f + expf(-zi));
                float fg = 1.f / (1.f + expf(-zf));
                float gg = tanhf(zg);
                float og = 1.f / (1.f + expf(-zo));
                float c = fg * cs[tid] + ig * gg;
                cs[tid] = c;
                float h = og * tanhf(c);
                __half hh = __float2half(h);
                g_h2rh[t & 1][b * HH + hu0 + u] = hh;
                g_a_h[((size_t)t * BB + b) * HH + hu0 + u] = hh;
                __threadfence();
            }
        }
        grid_barrier(NCTA);
    }
}

// ------------------------- HMMA dense GEMM (fp16, 3-stage pipeline) -------------
#define DARR 10240u          // bytes per sub-array (128*80)
#define DSTG 20480u          // bytes per stage (A|B)

__device__ __forceinline__ void dense_load_chunk(uint32_t sb, int m0, int n0, int c, int tid)
{
    const uint32_t stg = sb + (uint32_t)(c % 3) * DSTG;
    const int kc0 = c * 32;
#pragma unroll
    for (int it = 0; it < 4; it++) {
        int u = tid + it * 256;          // 0..1023 16B units
        int arr = u >> 9;                // 0 A, 1 B
        int u2 = u & 511;
        int r = u2 >> 2, q = u2 & 3;
        const __half* g = arr ? g_b_h : g_a_h;
        int grow = arr ? n0 : m0;
        cp_async16(stg + (uint32_t)arr * DARR + (uint32_t)(r * 80 + q * 16),
                   g + (size_t)(grow + r) * HH + kc0 + q * 8);
    }
    cp_commit();
}

__global__ __launch_bounds__(256, 2)
void dense_kernel(const float* __restrict__ bd, float* __restrict__ out)
{
    extern __shared__ char smem[];
    const uint32_t sb = smem_u32(smem);
    const int tid = threadIdx.x;
    const int wid = tid >> 5;
    const int lane = tid & 31;
    const int n0 = blockIdx.x * 128;
    const int m0 = blockIdx.y * 128;
    const int wm = wid & 1;
    const int wn = wid >> 1;
    const int lrow = lane & 15;
    const int lsel = (lane >> 4) << 4;

    float acc[4][4][4];
#pragma unroll
    for (int mt = 0; mt < 4; mt++)
#pragma unroll
        for (int nt = 0; nt < 4; nt++)
#pragma unroll
            for (int e = 0; e < 4; e++) acc[mt][nt][e] = 0.f;

    dense_load_chunk(sb, m0, n0, 0, tid);
    dense_load_chunk(sb, m0, n0, 1, tid);

    for (int c = 0; c < 16; c++) {
        if (c < 15) cp_wait<1>(); else cp_wait<0>();
        __syncthreads();
        if (c + 2 < 16) dense_load_chunk(sb, m0, n0, c + 2, tid);

        const uint32_t stg = sb + (uint32_t)(c % 3) * DSTG;
        const uint32_t a_b = stg + (uint32_t)((wm * 64 + lrow) * 80) + lsel;
        const uint32_t b_b = stg + DARR + (uint32_t)((wn * 32 + lrow) * 80) + lsel;
#pragma unroll
        for (int s = 0; s < 2; s++) {
            uint32_t bf[2][4];
#pragma unroll
            for (int i = 0; i < 2; i++)
                ldm_x4(bf[i], b_b + (uint32_t)(i * 16 * 80 + s * 32));
#pragma unroll
            for (int mt = 0; mt < 4; mt++) {
                uint32_t a[4];
                ldm_x4(a, a_b + (uint32_t)(mt * 16 * 80 + s * 32));
#pragma unroll
                for (int nt = 0; nt < 4; nt++) {
                    uint32_t b0 = bf[nt >> 1][nt & 1];
                    uint32_t b1 = bf[nt >> 1][(nt & 1) + 2];
                    mma_f16(acc[mt][nt], a, b0, b1);
                }
            }
        }
    }

    // epilogue: direct stores with [t*16+b] -> [b*256+t] row remap
    const int g = lane >> 2;
    const int tig = lane & 3;
#pragma unroll
    for (int nt = 0; nt < 4; nt++) {
        int col = n0 + wn * 32 + nt * 8 + tig * 2;
        float b0 = __ldg(bd + col);
        float b1 = __ldg(bd + col + 1);
#pragma unroll
        for (int mt = 0; mt < 4; mt++) {
            int r0 = m0 + wm * 64 + mt * 16 + g;
            int r1 = r0 + 8;
            size_t o0 = (size_t)((r0 & 15) * 256 + (r0 >> 4));
            size_t o1 = (size_t)((r1 & 15) * 256 + (r1 >> 4));
            float2 v0 = make_float2(acc[mt][nt][0] + b0, acc[mt][nt][1] + b1);
            float2 v1 = make_float2(acc[mt][nt][2] + b0, acc[mt][nt][3] + b1);
            *(float2*)(out + o0 * VV + col) = v0;
            *(float2*)(out + o1 * VV + col) = v1;
        }
    }
}

// ------------------------- launch -----------------------------------------------
extern "C" void kernel_launch(void* const* d_in, const int* in_sizes, int n_in,
                              void* d_out, int out_size)
{
    const int*   tokens = (const int*)  d_in[0];
    const float* emb    = (const float*)d_in[1];
    const float* W1     = (const float*)d_in[2];
    const float* U1     = (const float*)d_in[3];
    const float* b1     = (const float*)d_in[4];
    const float* W2     = (const float*)d_in[5];
    const float* U2     = (const float*)d_in[6];
    const float* b2     = (const float*)d_in[7];
    const float* Wd     = (const float*)d_in[8];
    const float* bd     = (const float*)d_in[9];
    float* out = (float*)d_out;

    cudaFuncSetAttribute(dense_kernel, cudaFuncAttributeMaxDynamicSharedMemorySize,
                         (int)(3 * DSTG));
    cudaFuncSetAttribute(lstm_tc_kernel, cudaFuncAttributeMaxDynamicSharedMemorySize,
                         LSTM_SMEM);

    // 1) fused prep: xw1 GEMM + Wd transpose + U^T fp16
    prep_kernel<<<512 + 16000 + 3072, 256>>>(emb, W1, b1, tokens, Wd, U1, W2, U2);
    // 2) fused dual-layer LSTM on tensor cores (64 CTAs); layer 2 writes fp16 g_a_h
    lstm_tc_kernel<<<NCTA, 512, LSTM_SMEM>>>(b2);
    // 3) logits = h2 @ Wd + bd on HMMA tensor cores (fp16 single pass)
    dense_kernel<<<dim3(VV / 128, MROWS / 128), 256, 3 * DSTG>>>(bd, out);
}

// round 11
// speedup vs baseline: 2.1086x; 1.0412x over previous
#include <cuda_runtime.h>
#include <cuda_bf16.h>
#include <cuda_fp16.h>
#include <math.h>
#include <stdint.h>

// Problem constants
#define BB 16
#define TT 256
#define EE 256
#define HH 512
#define G4H 2048
#define VV 32000
#define MROWS 4096           // B*T, row r = t*16 + b
#define NCTA 64              // LSTM CTA count (8 hidden units each)

// ------------------------- scratch (no mallocs allowed) -------------------------
__device__ float g_xw[(size_t)MROWS * G4H];       // xw1 = emb@W1+b1
__device__ __half g_h1rh[2][BB * HH];             // h1 ping-pong (fp16)
__device__ __half g_h2rh[2][BB * HH];             // h2 ping-pong (fp16)
__device__ __half g_ut[3 * (size_t)G4H * HH];     // U1^T|W2^T|U2^T fp16 [gc][k]
__device__ unsigned g_bar_count;
__device__ unsigned g_bar_gen;

// fp16 operands for the tensor-core dense layer
__device__ __half g_a_h[(size_t)MROWS * HH];      // written by LSTM layer-2 gates
__device__ __half g_b_h[(size_t)VV * HH];         // [v][h] transposed Wd

// ------------------------- small PTX helpers ------------------------------------
__device__ __forceinline__ uint32_t smem_u32(const void* p) {
    uint32_t a;
    asm("{ .reg .u64 t; cvta.to.shared.u64 t, %1; cvt.u32.u64 %0, t; }" : "=r"(a) : "l"(p));
    return a;
}
__device__ __forceinline__ void cp_async16(uint32_t saddr, const void* gptr) {
    asm volatile("cp.async.cg.shared.global [%0], [%1], 16;"
                 :: "r"(saddr), "l"(__cvta_generic_to_global(gptr)) : "memory");
}
__device__ __forceinline__ void cp_commit() {
    asm volatile("cp.async.commit_group;" ::: "memory");
}
template<int N>
__device__ __forceinline__ void cp_wait() {
    asm volatile("cp.async.wait_group %0;" :: "n"(N) : "memory");
}
__device__ __forceinline__ void ldm_x4(uint32_t* r, uint32_t a) {
    asm volatile("ldmatrix.sync.aligned.m8n8.x4.shared.b16 {%0,%1,%2,%3}, [%4];"
                 : "=r"(r[0]), "=r"(r[1]), "=r"(r[2]), "=r"(r[3]) : "r"(a));
}
__device__ __forceinline__ void mma_f16(float* d, const uint32_t* a, uint32_t b0, uint32_t b1) {
    asm volatile(
        "mma.sync.aligned.m16n8k16.row.col.f32.f16.f16.f32 "
        "{%0,%1,%2,%3}, {%4,%5,%6,%7}, {%8,%9}, {%0,%1,%2,%3};"
        : "+f"(d[0]), "+f"(d[1]), "+f"(d[2]), "+f"(d[3])
        : "r"(a[0]), "r"(a[1]), "r"(a[2]), "r"(a[3]), "r"(b0), "r"(b1));
}
// fast transcendentals (MUFU.EX2 / MUFU.RCP based, rel err ~1e-6)
__device__ __forceinline__ float fsigmoid(float x) {
    return __fdividef(1.f, 1.f + __expf(-x));
}
__device__ __forceinline__ float ftanh(float x) {
    return 1.f - __fdividef(2.f, __expf(2.f * x) + 1.f);
}

// ------------------------- global barrier (known step target) -------------------
__device__ __forceinline__ void grid_barrier_step(int ncta, unsigned target) {
    __syncthreads();
    if (threadIdx.x == 0) {
        __threadfence();
        if (atomicAdd(&g_bar_count, 1u) == (unsigned)(ncta - 1)) {
            g_bar_count = 0;
            __threadfence();
            *(volatile unsigned*)&g_bar_gen = target;
        } else {
            while (*(volatile unsigned*)&g_bar_gen < target) { }
            __threadfence();
        }
    }
    __syncthreads();
}

// ------------------------- prep: sgemm0 + transB(Wd) + transU x3 ----------------
// blocks [0,512): xw1 GEMM tiles; [512,16512): Wd transpose; [16512,19584): U^T fp16
__global__ __launch_bounds__(256, 2)
void prep_kernel(const float* __restrict__ emb,
                 const float* __restrict__ W1,
                 const float* __restrict__ b1,
                 const int* __restrict__ tokens,
                 const float* __restrict__ Wd,
                 const float* __restrict__ U1,
                 const float* __restrict__ W2,
                 const float* __restrict__ U2)
{
    const int bid = blockIdx.x;
    const int tid = threadIdx.x;

    if (bid >= 16512) {
        // ---- transU role: U[512][2048] fp32 -> g_ut[mat][2048][512] fp16 ----
        __shared__ __half sh2[32][33];
        int tb = bid - 16512;
        int mat = tb >> 10;
        int t2 = tb & 1023;
        int k0 = (t2 & 15) * 32;
        int g0 = (t2 >> 4) * 32;
        const float* src = (mat == 0) ? U1 : (mat == 1) ? W2 : U2;
        int tx = tid & 31, ty = tid >> 5;
#pragma unroll
        for (int j = 0; j < 4; j++) {
            int kr = ty + j * 8;
            sh2[kr][tx] = __float2half(src[(size_t)(k0 + kr) * G4H + g0 + tx]);
        }
        __syncthreads();
#pragma unroll
        for (int j = 0; j < 4; j++) {
            int gr = ty + j * 8;
            g_ut[(size_t)mat * G4H * HH + (size_t)(g0 + gr) * HH + k0 + tx] = sh2[tx][gr];
        }
        return;
    }
    if (bid >= 512) {
        // ---- transB role: Wd[512][32000] -> g_b_h[32000][512] fp16 ----
        __shared__ __half sh[32][33];
        int tb = bid - 512;
        int v0 = (tb % 1000) * 32;
        int h0 = (tb / 1000) * 32;
        int tx = tid & 31, ty = tid >> 5;
#pragma unroll
        for (int j = 0; j < 4; j++) {
            int hr = ty + j * 8;
            sh[hr][tx] = __float2half(Wd[(size_t)(h0 + hr) * VV + v0 + tx]);
        }
        __syncthreads();
#pragma unroll
        for (int j = 0; j < 4; j++) {
            int vr = ty + j * 8;
            g_b_h[(size_t)(v0 + vr) * HH + h0 + tx] = sh[tx][vr];
        }
        return;
    }

    // ---- sgemm0 role (+ barrier state reset, graph-replay safe) ----
    if (bid == 0 && tid == 0) { g_bar_count = 0; g_bar_gen = 0; }

    const int K = EE, N = G4H;
    __shared__ float As[16][128];
    __shared__ float Bs[16][128];

    const int m0 = (bid >> 4) * 128;
    const int n0 = (bid & 15) * 128;
    const int rg = (tid >> 4) * 4;
    const int cg = (tid & 15) * 4;

    float acc[8][8];
#pragma unroll
    for (int i = 0; i < 8; i++)
#pragma unroll
        for (int j = 0; j < 8; j++) acc[i][j] = 0.f;

    for (int kt = 0; kt < K; kt += 16) {
        __syncthreads();
#pragma unroll
        for (int it = 0; it < 2; it++) {
            int item = tid + it * 256;
            int m = item >> 2;
            int kq = item & 3;
            int gr = m0 + m;
            int tok = tokens[((gr & 15) << 8) + (gr >> 4)];
            float4 v = *(const float4*)(emb + (size_t)tok * K + kt + kq * 4);
            As[kq * 4 + 0][m] = v.x;
            As[kq * 4 + 1][m] = v.y;
            As[kq * 4 + 2][m] = v.z;
            As[kq * 4 + 3][m] = v.w;
        }
#pragma unroll
        for (int it = 0; it < 2; it++) {
            int item = tid + it * 256;
            int k = item >> 5;
            int n4 = item & 31;
            float4 v = *(const float4*)(W1 + (size_t)(kt + k) * N + n0 + n4 * 4);
            *(float4*)&Bs[k][n4 * 4] = v;
        }
        __syncthreads();
#pragma unroll
        for (int kk = 0; kk < 16; kk++) {
            float4 a0 = *(const float4*)&As[kk][rg];
            float4 a1 = *(const float4*)&As[kk][64 + rg];
            float4 b0 = *(const float4*)&Bs[kk][cg];
            float4 b1 = *(const float4*)&Bs[kk][64 + cg];
            float a[8] = {a0.x, a0.y, a0.z, a0.w, a1.x, a1.y, a1.z, a1.w};
            float b[8] = {b0.x, b0.y, b0.z, b0.w, b1.x, b1.y, b1.z, b1.w};
#pragma unroll
            for (int i = 0; i < 8; i++)
#pragma unroll
                for (int j = 0; j < 8; j++)
                    acc[i][j] += a[i] * b[j];
        }
    }

    float bj[8];
#pragma unroll
    for (int j = 0; j < 4; j++) {
        bj[j]     = b1[n0 + cg + j];
        bj[4 + j] = b1[n0 + 64 + cg + j];
    }
#pragma unroll
    for (int i = 0; i < 8; i++) {
        int r = m0 + ((i < 4) ? (rg + i) : (64 + rg + i - 4));
        float4 o0, o1;
        o0.x = acc[i][0] + bj[0]; o0.y = acc[i][1] + bj[1];
        o0.z = acc[i][2] + bj[2]; o0.w = acc[i][3] + bj[3];
        o1.x = acc[i][4] + bj[4]; o1.y = acc[i][5] + bj[5];
        o1.z = acc[i][6] + bj[6]; o1.w = acc[i][7] + bj[7];
        *(float4*)&g_xw[(size_t)r * N + n0 + cg]      = o0;
        *(float4*)&g_xw[(size_t)r * N + n0 + 64 + cg] = o1;
    }
}

// ------------------------- fused dual-layer LSTM on tensor cores ----------------
// 64 CTAs x 512 threads (16 warps), persistent. CTA owns 8 hidden units for BOTH
// layers (32 gate cols per matrix). Step s: h1[s] (s<256), h2[s-1] (s>=1).
// 24 TC jobs = {U1,W2,U2} x {ntile 0,1} x {4 k-slices}; warp w: j=w, and j=16+w (w<8).
// Reduce + gates fused per warp: warp rb = batch row, lane rn = gate col; gate
// quads {u,8+u,16+u,24+u} gathered via shfl; cell state in registers.
// SMEM: Bsl 0 (99840) | h1st 99840 (16640) | h2st 116480 (16640) | zp 133120 (24576)
#define LSTM_SMEM 157696
__global__ __launch_bounds__(512, 1)
void lstm_tc_kernel(const float* __restrict__ b2)
{
    extern __shared__ char lsm[];
    char* Bsl = lsm;
    char* h1st = lsm + 99840;
    char* h2st = lsm + 116480;
    float* zp = (float*)(lsm + 133120);

    const int tid = threadIdx.x;
    const int wid = tid >> 5;
    const int lane = tid & 31;
    const int ct = blockIdx.x;
    const int hu0 = ct * 8;
    const uint32_t Bsl_a = smem_u32(Bsl);
    const uint32_t h1_a = smem_u32(h1st);
    const uint32_t h2_a = smem_u32(h2st);

    // ---- init: load B slices (g_ut rows are coalesced 1KB) ----
    for (int i = tid; i < 6144; i += 512) {
        int mat = i >> 11;
        int rem = i & 2047;
        int n = rem >> 6;                 // 0..31 gate col idx (g*8+u)
        int ch = rem & 63;
        int gc = (n >> 3) * HH + hu0 + (n & 7);
        cp_async16(Bsl_a + (uint32_t)(mat * 33280 + n * 1040 + ch * 16),
                   g_ut + (size_t)mat * G4H * HH + (size_t)gc * HH + ch * 8);
    }
    cp_commit();
    // zero h stages (2 x 16640 B contiguous at h1st)
    for (int i = tid; i < 2080; i += 512)
        *(uint4*)(h1st + i * 16) = make_uint4(0, 0, 0, 0);
    cp_wait<0>();
    __syncthreads();

    // reduce-role constants: thread -> (b = tid/32 = warp, n = tid%32 = lane)
    const int rb = wid;
    const int rn = lane;
    const int rgc = (rn >> 3) * HH + hu0 + (rn & 7);
    const float b2v = __ldg(b2 + rgc);
    const int u7 = rn & 7;

    // register-resident cell state: lanes 0-7 hold c1[u], lanes 8-15 hold c2[u]
    float creg = 0.f;

    const uint32_t lrow = (uint32_t)(lane & 15) * 1040u;
    const uint32_t lsel = (uint32_t)((lane >> 4) << 4);

    for (int s = 0; s <= TT; s++) {
        // prefetch xw operand early (consumed in reduce)
        float xwv = (s < TT) ? __ldg(&g_xw[((size_t)s * BB + rb) * G4H + rgc]) : 0.f;

        // ---- stage h1[s-1], h2[s-2] as fp16 (1024 chunks each) ----
        if (s >= 1) {
            const __half* hp = g_h1rh[(s - 1) & 1];
#pragma unroll
            for (int i = 0; i < 2; i++) {
                int u = tid + i * 512;        // 0..1023
                int b = u >> 6, ch = u & 63;
                cp_async16(h1_a + (uint32_t)(b * 1040 + ch * 16), hp + b * HH + ch * 8);
            }
            if (s >= 2) {
                const __half* hq = g_h2rh[s & 1];
#pragma unroll
                for (int i = 0; i < 2; i++) {
                    int u = tid + i * 512;
                    int b = u >> 6, ch = u & 63;
                    cp_async16(h2_a + (uint32_t)(b * 1040 + ch * 16), hq + b * HH + ch * 8);
                }
            }
            cp_commit();
            cp_wait<0>();
        }
        __syncthreads();

        // ---- tensor-core matvecs: job j = (mat, ntile, ksl) ----
#pragma unroll
        for (int jj = 0; jj < 2; jj++) {
            int j = (jj == 0) ? wid : (16 + wid);
            if (j < 24) {
                int mat = j >> 3;
                int rem = j & 7;
                int ntile = rem >> 2;
                int ksl = rem & 3;
                uint32_t Ab = ((mat == 2) ? h2_a : h1_a) + (uint32_t)(ksl * 256) + lrow + lsel;
                uint32_t Bb = Bsl_a + (uint32_t)(mat * 33280 + ntile * 16 * 1040 + ksl * 256)
                              + lrow + lsel;
                float acc[2][4] = {{0.f, 0.f, 0.f, 0.f}, {0.f, 0.f, 0.f, 0.f}};
#pragma unroll
                for (int c = 0; c < 8; c++) {
                    uint32_t a[4], bf[4];
                    ldm_x4(a, Ab + (uint32_t)(c * 32));
                    ldm_x4(bf, Bb + (uint32_t)(c * 32));
                    mma_f16(acc[0], a, bf[0], bf[2]);
                    mma_f16(acc[1], a, bf[1], bf[3]);
                }
                int r0 = lane >> 2, c0 = (lane & 3) * 2;
                float* zj = zp + j * 256;
#pragma unroll
                for (int nt = 0; nt < 2; nt++) {
                    zj[r0 * 16 + nt * 8 + c0]           = acc[nt][0];
                    zj[r0 * 16 + nt * 8 + c0 + 1]       = acc[nt][1];
                    zj[(r0 + 8) * 16 + nt * 8 + c0]     = acc[nt][2];
                    zj[(r0 + 8) * 16 + nt * 8 + c0 + 1] = acc[nt][3];
                }
            }
        }
        __syncthreads();

        // ---- fused reduce + gates (per-warp, shuffle gather) ----
        {
            int ntile = rn >> 4;
            int o16 = rb * 16 + (rn & 15);
            float z1 = xwv, z2 = b2v;
#pragma unroll
            for (int ksl = 0; ksl < 4; ksl++) {
                z1 += zp[(ntile * 4 + ksl) * 256 + o16];
                z2 += zp[(8 + ntile * 4 + ksl) * 256 + o16]
                    + zp[(16 + ntile * 4 + ksl) * 256 + o16];
            }
            // gather gate quads: unit u gates live in lanes {u, 8+u, 16+u, 24+u}
            float a0 = __shfl_sync(0xffffffffu, z1, u7);
            float a1 = __shfl_sync(0xffffffffu, z1, 8 + u7);
            float a2 = __shfl_sync(0xffffffffu, z1, 16 + u7);
            float a3 = __shfl_sync(0xffffffffu, z1, 24 + u7);
            float d0 = __shfl_sync(0xffffffffu, z2, u7);
            float d1 = __shfl_sync(0xffffffffu, z2, 8 + u7);
            float d2 = __shfl_sync(0xffffffffu, z2, 16 + u7);
            float d3 = __shfl_sync(0xffffffffu, z2, 24 + u7);

            if (rn < 8) {
                if (s < TT) {
                    float ig = fsigmoid(a0);
                    float fg = fsigmoid(a1);
                    float gg = ftanh(a2);
                    float og = fsigmoid(a3);
                    creg = fg * creg + ig * gg;
                    g_h1rh[s & 1][rb * HH + hu0 + u7] = __float2half(og * ftanh(creg));
                }
            } else if (rn < 16) {
                if (s >= 1) {
                    int t = s - 1;
                    float ig = fsigmoid(d0);
                    float fg = fsigmoid(d1);
                    float gg = ftanh(d2);
                    float og = fsigmoid(d3);
                    creg = fg * creg + ig * gg;
                    float h = og * ftanh(creg);
                    __half hh = __float2half(h);
                    g_h2rh[t & 1][rb * HH + hu0 + u7] = hh;
                    g_a_h[((size_t)t * BB + rb) * HH + hu0 + u7] = hh;
                }
            }
        }

        if (s < TT) grid_barrier_step(NCTA, (unsigned)(s + 1));
    }
}

// ------------------------- HMMA dense GEMM (fp16, 3-stage pipeline) -------------
#define DARR 10240u          // bytes per sub-array (128*80)
#define DSTG 20480u          // bytes per stage (A|B)

__device__ __forceinline__ void dense_load_chunk(uint32_t sb, int m0, int n0, int c, int tid)
{
    const uint32_t stg = sb + (uint32_t)(c % 3) * DSTG;
    const int kc0 = c * 32;
#pragma unroll
    for (int it = 0; it < 4; it++) {
        int u = tid + it * 256;          // 0..1023 16B units
        int arr = u >> 9;                // 0 A, 1 B
        int u2 = u & 511;
        int r = u2 >> 2, q = u2 & 3;
        const __half* g = arr ? g_b_h : g_a_h;
        int grow = arr ? n0 : m0;
        cp_async16(stg + (uint32_t)arr * DARR + (uint32_t)(r * 80 + q * 16),
                   g + (size_t)(grow + r) * HH + kc0 + q * 8);
    }
    cp_commit();
}

__global__ __launch_bounds__(256, 2)
void dense_kernel(const float* __restrict__ bd, float* __restrict__ out)
{
    extern __shared__ char smem[];
    const uint32_t sb = smem_u32(smem);
    const int tid = threadIdx.x;
    const int wid = tid >> 5;
    const int lane = tid & 31;
    const int n0 = blockIdx.x * 128;
    const int m0 = blockIdx.y * 128;
    const int wm = wid & 1;
    const int wn = wid >> 1;
    const int lrow = lane & 15;
    const int lsel = (lane >> 4) << 4;

    float acc[4][4][4];
#pragma unroll
    for (int mt = 0; mt < 4; mt++)
#pragma unroll
        for (int nt = 0; nt < 4; nt++)
#pragma unroll
            for (int e = 0; e < 4; e++) acc[mt][nt][e] = 0.f;

    dense_load_chunk(sb, m0, n0, 0, tid);
    dense_load_chunk(sb, m0, n0, 1, tid);

    for (int c = 0; c < 16; c++) {
        if (c < 15) cp_wait<1>(); else cp_wait<0>();
        __syncthreads();
        if (c + 2 < 16) dense_load_chunk(sb, m0, n0, c + 2, tid);

        const uint32_t stg = sb + (uint32_t)(c % 3) * DSTG;
        const uint32_t a_b = stg + (uint32_t)((wm * 64 + lrow) * 80) + lsel;
        const uint32_t b_b = stg + DARR + (uint32_t)((wn * 32 + lrow) * 80) + lsel;
#pragma unroll
        for (int s = 0; s < 2; s++) {
            uint32_t bf[2][4];
#pragma unroll
            for (int i = 0; i < 2; i++)
                ldm_x4(bf[i], b_b + (uint32_t)(i * 16 * 80 + s * 32));
#pragma unroll
            for (int mt = 0; mt < 4; mt++) {
                uint32_t a[4];
                ldm_x4(a, a_b + (uint32_t)(mt * 16 * 80 + s * 32));
#pragma unroll
                for (int nt = 0; nt < 4; nt++) {
                    uint32_t b0 = bf[nt >> 1][nt & 1];
                    uint32_t b1 = bf[nt >> 1][(nt & 1) + 2];
                    mma_f16(acc[mt][nt], a, b0, b1);
                }
            }
        }
    }

    // epilogue: direct stores with [t*16+b] -> [b*256+t] row remap
    const int g = lane >> 2;
    const int tig = lane & 3;
#pragma unroll
    for (int nt = 0; nt < 4; nt++) {
        int col = n0 + wn * 32 + nt * 8 + tig * 2;
        float b0 = __ldg(bd + col);
        float b1 = __ldg(bd + col + 1);
#pragma unroll
        for (int mt = 0; mt < 4; mt++) {
            int r0 = m0 + wm * 64 + mt * 16 + g;
            int r1 = r0 + 8;
            size_t o0 = (size_t)((r0 & 15) * 256 + (r0 >> 4));
            size_t o1 = (size_t)((r1 & 15) * 256 + (r1 >> 4));
            float2 v0 = make_float2(acc[mt][nt][0] + b0, acc[mt][nt][1] + b1);
            float2 v1 = make_float2(acc[mt][nt][2] + b0, acc[mt][nt][3] + b1);
            *(float2*)(out + o0 * VV + col) = v0;
            *(float2*)(out + o1 * VV + col) = v1;
        }
    }
}

// ------------------------- launch -----------------------------------------------
extern "C" void kernel_launch(void* const* d_in, const int* in_sizes, int n_in,
                              void* d_out, int out_size)
{
    const int*   tokens = (const int*)  d_in[0];
    const float* emb    = (const float*)d_in[1];
    const float* W1     = (const float*)d_in[2];
    const float* U1     = (const float*)d_in[3];
    const float* b1     = (const float*)d_in[4];
    const float* W2     = (const float*)d_in[5];
    const float* U2     = (const float*)d_in[6];
    const float* b2     = (const float*)d_in[7];
    const float* Wd     = (const float*)d_in[8];
    const float* bd     = (const float*)d_in[9];
    float* out = (float*)d_out;

    cudaFuncSetAttribute(dense_kernel, cudaFuncAttributeMaxDynamicSharedMemorySize,
                         (int)(3 * DSTG));
    cudaFuncSetAttribute(lstm_tc_kernel, cudaFuncAttributeMaxDynamicSharedMemorySize,
                         LSTM_SMEM);

    // 1) fused prep: xw1 GEMM (+barrier reset) + Wd transpose + U^T fp16
    prep_kernel<<<512 + 16000 + 3072, 256>>>(emb, W1, b1, tokens, Wd, U1, W2, U2);
    // 2) fused dual-layer LSTM on tensor cores (64 CTAs); layer 2 writes fp16 g_a_h
    lstm_tc_kernel<<<NCTA, 512, LSTM_SMEM>>>(b2);
    // 3) logits = h2 @ Wd + bd on HMMA tensor cores (fp16 single pass)
    dense_kernel<<<dim3(VV / 128, MROWS / 128), 256, 3 * DSTG>>>(bd, out);
}

// round 12
// speedup vs baseline: 2.3268x; 1.1035x over previous
#include <cuda_runtime.h>
#include <cuda_bf16.h>
#include <cuda_fp16.h>
#include <math.h>
#include <stdint.h>

// Problem constants
#define BB 16
#define TT 256
#define EE 256
#define HH 512
#define G4H 2048
#define VV 32000
#define MROWS 4096           // B*T, row r = t*16 + b
#define NCTA 64              // LSTM CTA count (8 hidden units each)

// ------------------------- scratch (no mallocs allowed) -------------------------
__device__ float g_xw[(size_t)MROWS * G4H];       // xw1 = emb@W1+b1
__device__ __half g_h1rh[2][BB * HH];             // h1 ping-pong (fp16)
__device__ __half g_h2rh[2][BB * HH];             // h2 ping-pong (fp16)
__device__ __half g_ut[3 * (size_t)G4H * HH];     // U1^T|W2^T|U2^T fp16 [gc][k]
__device__ unsigned g_gcnt[8 * 64];               // 8 group counters, 256B apart

// fp16 operands for the tensor-core dense layer
__device__ __half g_a_h[(size_t)MROWS * HH];      // written by LSTM layer-2 gates
__device__ __half g_b_h[(size_t)VV * HH];         // [v][h] transposed Wd

// ------------------------- small PTX helpers ------------------------------------
__device__ __forceinline__ uint32_t smem_u32(const void* p) {
    uint32_t a;
    asm("{ .reg .u64 t; cvta.to.shared.u64 t, %1; cvt.u32.u64 %0, t; }" : "=r"(a) : "l"(p));
    return a;
}
__device__ __forceinline__ void cp_async16(uint32_t saddr, const void* gptr) {
    asm volatile("cp.async.cg.shared.global [%0], [%1], 16;"
                 :: "r"(saddr), "l"(__cvta_generic_to_global(gptr)) : "memory");
}
__device__ __forceinline__ void cp_commit() {
    asm volatile("cp.async.commit_group;" ::: "memory");
}
template<int N>
__device__ __forceinline__ void cp_wait() {
    asm volatile("cp.async.wait_group %0;" :: "n"(N) : "memory");
}
__device__ __forceinline__ void ldm_x4(uint32_t* r, uint32_t a) {
    asm volatile("ldmatrix.sync.aligned.m8n8.x4.shared.b16 {%0,%1,%2,%3}, [%4];"
                 : "=r"(r[0]), "=r"(r[1]), "=r"(r[2]), "=r"(r[3]) : "r"(a));
}
__device__ __forceinline__ void mma_f16(float* d, const uint32_t* a, uint32_t b0, uint32_t b1) {
    asm volatile(
        "mma.sync.aligned.m16n8k16.row.col.f32.f16.f16.f32 "
        "{%0,%1,%2,%3}, {%4,%5,%6,%7}, {%8,%9}, {%0,%1,%2,%3};"
        : "+f"(d[0]), "+f"(d[1]), "+f"(d[2]), "+f"(d[3])
        : "r"(a[0]), "r"(a[1]), "r"(a[2]), "r"(a[3]), "r"(b0), "r"(b1));
}
// fast transcendentals (MUFU.EX2 / MUFU.RCP based, rel err ~1e-6)
__device__ __forceinline__ float fsigmoid(float x) {
    return __fdividef(1.f, 1.f + __expf(-x));
}
__device__ __forceinline__ float ftanh(float x) {
    return 1.f - __fdividef(2.f, __expf(2.f * x) + 1.f);
}

// ------------------------- grouped-counter barrier ------------------------------
// 64 CTAs, 8 counters (one per CTA group ct&7) spaced 256B (distinct LTS slices).
// Arrival: fire-and-forget atomicAdd (REDG). Completion: warp 0 polls all 8
// counters (lane l -> counter l&7) until every one reaches 8*(s+1).
__device__ __forceinline__ void grid_barrier_grp(unsigned target8, int lane, int wid, int ct) {
    __syncthreads();
    if (wid == 0) {
        __threadfence();
        if (lane == 0)
            atomicAdd(&g_gcnt[(ct & 7) * 64], 1u);
        volatile unsigned* cp = &g_gcnt[(lane & 7) * 64];
        bool ok;
        do {
            unsigned v = *cp;
            ok = __all_sync(0xffffffffu, v >= target8);
        } while (!ok);
        __threadfence();
    }
    __syncthreads();
}

// ------------------------- prep: sgemm0 + transB(Wd) + transU x3 ----------------
// blocks [0,512): xw1 GEMM tiles; [512,16512): Wd transpose; [16512,19584): U^T fp16
__global__ __launch_bounds__(256, 2)
void prep_kernel(const float* __restrict__ emb,
                 const float* __restrict__ W1,
                 const float* __restrict__ b1,
                 const int* __restrict__ tokens,
                 const float* __restrict__ Wd,
                 const float* __restrict__ U1,
                 const float* __restrict__ W2,
                 const float* __restrict__ U2)
{
    const int bid = blockIdx.x;
    const int tid = threadIdx.x;

    if (bid >= 16512) {
        // ---- transU role: U[512][2048] fp32 -> g_ut[mat][2048][512] fp16 ----
        __shared__ __half sh2[32][33];
        int tb = bid - 16512;
        int mat = tb >> 10;
        int t2 = tb & 1023;
        int k0 = (t2 & 15) * 32;
        int g0 = (t2 >> 4) * 32;
        const float* src = (mat == 0) ? U1 : (mat == 1) ? W2 : U2;
        int tx = tid & 31, ty = tid >> 5;
#pragma unroll
        for (int j = 0; j < 4; j++) {
            int kr = ty + j * 8;
            sh2[kr][tx] = __float2half(src[(size_t)(k0 + kr) * G4H + g0 + tx]);
        }
        __syncthreads();
#pragma unroll
        for (int j = 0; j < 4; j++) {
            int gr = ty + j * 8;
            g_ut[(size_t)mat * G4H * HH + (size_t)(g0 + gr) * HH + k0 + tx] = sh2[tx][gr];
        }
        return;
    }
    if (bid >= 512) {
        // ---- transB role: Wd[512][32000] -> g_b_h[32000][512] fp16 ----
        __shared__ __half sh[32][33];
        int tb = bid - 512;
        int v0 = (tb % 1000) * 32;
        int h0 = (tb / 1000) * 32;
        int tx = tid & 31, ty = tid >> 5;
#pragma unroll
        for (int j = 0; j < 4; j++) {
            int hr = ty + j * 8;
            sh[hr][tx] = __float2half(Wd[(size_t)(h0 + hr) * VV + v0 + tx]);
        }
        __syncthreads();
#pragma unroll
        for (int j = 0; j < 4; j++) {
            int vr = ty + j * 8;
            g_b_h[(size_t)(v0 + vr) * HH + h0 + tx] = sh[tx][vr];
        }
        return;
    }

    // ---- sgemm0 role (+ barrier counter reset, graph-replay safe) ----
    if (bid == 0 && tid < 8) g_gcnt[tid * 64] = 0;

    const int K = EE, N = G4H;
    __shared__ float As[16][128];
    __shared__ float Bs[16][128];

    const int m0 = (bid >> 4) * 128;
    const int n0 = (bid & 15) * 128;
    const int rg = (tid >> 4) * 4;
    const int cg = (tid & 15) * 4;

    float acc[8][8];
#pragma unroll
    for (int i = 0; i < 8; i++)
#pragma unroll
        for (int j = 0; j < 8; j++) acc[i][j] = 0.f;

    for (int kt = 0; kt < K; kt += 16) {
        __syncthreads();
#pragma unroll
        for (int it = 0; it < 2; it++) {
            int item = tid + it * 256;
            int m = item >> 2;
            int kq = item & 3;
            int gr = m0 + m;
            int tok = tokens[((gr & 15) << 8) + (gr >> 4)];
            float4 v = *(const float4*)(emb + (size_t)tok * K + kt + kq * 4);
            As[kq * 4 + 0][m] = v.x;
            As[kq * 4 + 1][m] = v.y;
            As[kq * 4 + 2][m] = v.z;
            As[kq * 4 + 3][m] = v.w;
        }
#pragma unroll
        for (int it = 0; it < 2; it++) {
            int item = tid + it * 256;
            int k = item >> 5;
            int n4 = item & 31;
            float4 v = *(const float4*)(W1 + (size_t)(kt + k) * N + n0 + n4 * 4);
            *(float4*)&Bs[k][n4 * 4] = v;
        }
        __syncthreads();
#pragma unroll
        for (int kk = 0; kk < 16; kk++) {
            float4 a0 = *(const float4*)&As[kk][rg];
            float4 a1 = *(const float4*)&As[kk][64 + rg];
            float4 b0 = *(const float4*)&Bs[kk][cg];
            float4 b1 = *(const float4*)&Bs[kk][64 + cg];
            float a[8] = {a0.x, a0.y, a0.z, a0.w, a1.x, a1.y, a1.z, a1.w};
            float b[8] = {b0.x, b0.y, b0.z, b0.w, b1.x, b1.y, b1.z, b1.w};
#pragma unroll
            for (int i = 0; i < 8; i++)
#pragma unroll
                for (int j = 0; j < 8; j++)
                    acc[i][j] += a[i] * b[j];
        }
    }

    float bj[8];
#pragma unroll
    for (int j = 0; j < 4; j++) {
        bj[j]     = b1[n0 + cg + j];
        bj[4 + j] = b1[n0 + 64 + cg + j];
    }
#pragma unroll
    for (int i = 0; i < 8; i++) {
        int r = m0 + ((i < 4) ? (rg + i) : (64 + rg + i - 4));
        float4 o0, o1;
        o0.x = acc[i][0] + bj[0]; o0.y = acc[i][1] + bj[1];
        o0.z = acc[i][2] + bj[2]; o0.w = acc[i][3] + bj[3];
        o1.x = acc[i][4] + bj[4]; o1.y = acc[i][5] + bj[5];
        o1.z = acc[i][6] + bj[6]; o1.w = acc[i][7] + bj[7];
        *(float4*)&g_xw[(size_t)r * N + n0 + cg]      = o0;
        *(float4*)&g_xw[(size_t)r * N + n0 + 64 + cg] = o1;
    }
}

// ------------------------- fused dual-layer LSTM on tensor cores ----------------
// 64 CTAs x 512 threads (16 warps), persistent. CTA owns 8 hidden units for BOTH
// layers (32 gate cols per matrix). Step s: h1[s] (s<256), h2[s-1] (s>=1).
// 24 TC jobs = {U1,W2,U2} x {ntile 0,1} x {4 k-slices}; warp w: j=w, and j=16+w (w<8).
// Reduce + gates fused per warp (shfl gather); cell state in registers.
// SMEM: Bsl 0 (99840) | h1st 99840 (16640) | h2st 116480 (16640) | zp 133120 (24576)
#define LSTM_SMEM 157696
__global__ __launch_bounds__(512, 1)
void lstm_tc_kernel(const float* __restrict__ b2)
{
    extern __shared__ char lsm[];
    char* Bsl = lsm;
    char* h1st = lsm + 99840;
    char* h2st = lsm + 116480;
    float* zp = (float*)(lsm + 133120);

    const int tid = threadIdx.x;
    const int wid = tid >> 5;
    const int lane = tid & 31;
    const int ct = blockIdx.x;
    const int hu0 = ct * 8;
    const uint32_t Bsl_a = smem_u32(Bsl);
    const uint32_t h1_a = smem_u32(h1st);
    const uint32_t h2_a = smem_u32(h2st);

    // ---- init: load B slices (g_ut rows are coalesced 1KB) ----
    for (int i = tid; i < 6144; i += 512) {
        int mat = i >> 11;
        int rem = i & 2047;
        int n = rem >> 6;                 // 0..31 gate col idx (g*8+u)
        int ch = rem & 63;
        int gc = (n >> 3) * HH + hu0 + (n & 7);
        cp_async16(Bsl_a + (uint32_t)(mat * 33280 + n * 1040 + ch * 16),
                   g_ut + (size_t)mat * G4H * HH + (size_t)gc * HH + ch * 8);
    }
    cp_commit();
    // zero h stages (2 x 16640 B contiguous at h1st)
    for (int i = tid; i < 2080; i += 512)
        *(uint4*)(h1st + i * 16) = make_uint4(0, 0, 0, 0);
    cp_wait<0>();
    __syncthreads();

    // reduce-role constants: thread -> (b = tid/32 = warp, n = tid%32 = lane)
    const int rb = wid;
    const int rn = lane;
    const int rgc = (rn >> 3) * HH + hu0 + (rn & 7);
    const float b2v = __ldg(b2 + rgc);
    const int u7 = rn & 7;

    // register-resident cell state: lanes 0-7 hold c1[u], lanes 8-15 hold c2[u]
    float creg = 0.f;

    const uint32_t lrow = (uint32_t)(lane & 15) * 1040u;
    const uint32_t lsel = (uint32_t)((lane >> 4) << 4);

    for (int s = 0; s <= TT; s++) {
        // prefetch xw operand early (consumed in reduce)
        float xwv = (s < TT) ? __ldg(&g_xw[((size_t)s * BB + rb) * G4H + rgc]) : 0.f;

        // ---- stage h1[s-1], h2[s-2] as fp16 (1024 chunks each) ----
        if (s >= 1) {
            const __half* hp = g_h1rh[(s - 1) & 1];
#pragma unroll
            for (int i = 0; i < 2; i++) {
                int u = tid + i * 512;        // 0..1023
                int b = u >> 6, ch = u & 63;
                cp_async16(h1_a + (uint32_t)(b * 1040 + ch * 16), hp + b * HH + ch * 8);
            }
            if (s >= 2) {
                const __half* hq = g_h2rh[s & 1];
#pragma unroll
                for (int i = 0; i < 2; i++) {
                    int u = tid + i * 512;
                    int b = u >> 6, ch = u & 63;
                    cp_async16(h2_a + (uint32_t)(b * 1040 + ch * 16), hq + b * HH + ch * 8);
                }
            }
            cp_commit();
            cp_wait<0>();
        }
        __syncthreads();

        // ---- tensor-core matvecs: job j = (mat, ntile, ksl) ----
#pragma unroll
        for (int jj = 0; jj < 2; jj++) {
            int j = (jj == 0) ? wid : (16 + wid);
            if (j < 24) {
                int mat = j >> 3;
                int rem = j & 7;
                int ntile = rem >> 2;
                int ksl = rem & 3;
                uint32_t Ab = ((mat == 2) ? h2_a : h1_a) + (uint32_t)(ksl * 256) + lrow + lsel;
                uint32_t Bb = Bsl_a + (uint32_t)(mat * 33280 + ntile * 16 * 1040 + ksl * 256)
                              + lrow + lsel;
                float acc[2][4] = {{0.f, 0.f, 0.f, 0.f}, {0.f, 0.f, 0.f, 0.f}};
#pragma unroll
                for (int c = 0; c < 8; c++) {
                    uint32_t a[4], bf[4];
                    ldm_x4(a, Ab + (uint32_t)(c * 32));
                    ldm_x4(bf, Bb + (uint32_t)(c * 32));
                    mma_f16(acc[0], a, bf[0], bf[2]);
                    mma_f16(acc[1], a, bf[1], bf[3]);
                }
                int r0 = lane >> 2, c0 = (lane & 3) * 2;
                float* zj = zp + j * 256;
#pragma unroll
                for (int nt = 0; nt < 2; nt++) {
                    zj[r0 * 16 + nt * 8 + c0]           = acc[nt][0];
                    zj[r0 * 16 + nt * 8 + c0 + 1]       = acc[nt][1];
                    zj[(r0 + 8) * 16 + nt * 8 + c0]     = acc[nt][2];
                    zj[(r0 + 8) * 16 + nt * 8 + c0 + 1] = acc[nt][3];
                }
            }
        }
        __syncthreads();

        // ---- fused reduce + gates (per-warp, shuffle gather) ----
        {
            int ntile = rn >> 4;
            int o16 = rb * 16 + (rn & 15);
            float z1 = xwv, z2 = b2v;
#pragma unroll
            for (int ksl = 0; ksl < 4; ksl++) {
                z1 += zp[(ntile * 4 + ksl) * 256 + o16];
                z2 += zp[(8 + ntile * 4 + ksl) * 256 + o16]
                    + zp[(16 + ntile * 4 + ksl) * 256 + o16];
            }
            // gather gate quads: unit u gates live in lanes {u, 8+u, 16+u, 24+u}
            float a0 = __shfl_sync(0xffffffffu, z1, u7);
            float a1 = __shfl_sync(0xffffffffu, z1, 8 + u7);
            float a2 = __shfl_sync(0xffffffffu, z1, 16 + u7);
            float a3 = __shfl_sync(0xffffffffu, z1, 24 + u7);
            float d0 = __shfl_sync(0xffffffffu, z2, u7);
            float d1 = __shfl_sync(0xffffffffu, z2, 8 + u7);
            float d2 = __shfl_sync(0xffffffffu, z2, 16 + u7);
            float d3 = __shfl_sync(0xffffffffu, z2, 24 + u7);

            if (rn < 8) {
                if (s < TT) {
                    float ig = fsigmoid(a0);
                    float fg = fsigmoid(a1);
                    float gg = ftanh(a2);
                    float og = fsigmoid(a3);
                    creg = fg * creg + ig * gg;
                    g_h1rh[s & 1][rb * HH + hu0 + u7] = __float2half(og * ftanh(creg));
                }
            } else if (rn < 16) {
                if (s >= 1) {
                    int t = s - 1;
                    float ig = fsigmoid(d0);
                    float fg = fsigmoid(d1);
                    float gg = ftanh(d2);
                    float og = fsigmoid(d3);
                    creg = fg * creg + ig * gg;
                    float h = og * ftanh(creg);
                    __half hh = __float2half(h);
                    g_h2rh[t & 1][rb * HH + hu0 + u7] = hh;
                    g_a_h[((size_t)t * BB + rb) * HH + hu0 + u7] = hh;
                }
            }
        }

        if (s < TT) grid_barrier_grp((unsigned)(8 * (s + 1)), lane, wid, ct);
    }
}

// ------------------------- HMMA dense GEMM (fp16, 3-stage pipeline) -------------
#define DARR 10240u          // bytes per sub-array (128*80)
#define DSTG 20480u          // bytes per stage (A|B)

__device__ __forceinline__ void dense_load_chunk(uint32_t sb, int m0, int n0, int c, int tid)
{
    const uint32_t stg = sb + (uint32_t)(c % 3) * DSTG;
    const int kc0 = c * 32;
#pragma unroll
    for (int it = 0; it < 4; it++) {
        int u = tid + it * 256;          // 0..1023 16B units
        int arr = u >> 9;                // 0 A, 1 B
        int u2 = u & 511;
        int r = u2 >> 2, q = u2 & 3;
        const __half* g = arr ? g_b_h : g_a_h;
        int grow = arr ? n0 : m0;
        cp_async16(stg + (uint32_t)arr * DARR + (uint32_t)(r * 80 + q * 16),
                   g + (size_t)(grow + r) * HH + kc0 + q * 8);
    }
    cp_commit();
}

__global__ __launch_bounds__(256, 2)
void dense_kernel(const float* __restrict__ bd, float* __restrict__ out)
{
    extern __shared__ char smem[];
    const uint32_t sb = smem_u32(smem);
    const int tid = threadIdx.x;
    const int wid = tid >> 5;
    const int lane = tid & 31;
    const int n0 = blockIdx.x * 128;
    const int m0 = blockIdx.y * 128;
    const int wm = wid & 1;
    const int wn = wid >> 1;
    const int lrow = lane & 15;
    const int lsel = (lane >> 4) << 4;

    float acc[4][4][4];
#pragma unroll
    for (int mt = 0; mt < 4; mt++)
#pragma unroll
        for (int nt = 0; nt < 4; nt++)
#pragma unroll
            for (int e = 0; e < 4; e++) acc[mt][nt][e] = 0.f;

    dense_load_chunk(sb, m0, n0, 0, tid);
    dense_load_chunk(sb, m0, n0, 1, tid);

    for (int c = 0; c < 16; c++) {
        if (c < 15) cp_wait<1>(); else cp_wait<0>();
        __syncthreads();
        if (c + 2 < 16) dense_load_chunk(sb, m0, n0, c + 2, tid);

        const uint32_t stg = sb + (uint32_t)(c % 3) * DSTG;
        const uint32_t a_b = stg + (uint32_t)((wm * 64 + lrow) * 80) + lsel;
        const uint32_t b_b = stg + DARR + (uint32_t)((wn * 32 + lrow) * 80) + lsel;
#pragma unroll
        for (int s = 0; s < 2; s++) {
            uint32_t bf[2][4];
#pragma unroll
            for (int i = 0; i < 2; i++)
                ldm_x4(bf[i], b_b + (uint32_t)(i * 16 * 80 + s * 32));
#pragma unroll
            for (int mt = 0; mt < 4; mt++) {
                uint32_t a[4];
                ldm_x4(a, a_b + (uint32_t)(mt * 16 * 80 + s * 32));
#pragma unroll
                for (int nt = 0; nt < 4; nt++) {
                    uint32_t b0 = bf[nt >> 1][nt & 1];
                    uint32_t b1 = bf[nt >> 1][(nt & 1) + 2];
                    mma_f16(acc[mt][nt], a, b0, b1);
                }
            }
        }
    }

    // epilogue: direct stores with [t*16+b] -> [b*256+t] row remap
    const int g = lane >> 2;
    const int tig = lane & 3;
#pragma unroll
    for (int nt = 0; nt < 4; nt++) {
        int col = n0 + wn * 32 + nt * 8 + tig * 2;
        float b0 = __ldg(bd + col);
        float b1 = __ldg(bd + col + 1);
#pragma unroll
        for (int mt = 0; mt < 4; mt++) {
            int r0 = m0 + wm * 64 + mt * 16 + g;
            int r1 = r0 + 8;
            size_t o0 = (size_t)((r0 & 15) * 256 + (r0 >> 4));
            size_t o1 = (size_t)((r1 & 15) * 256 + (r1 >> 4));
            float2 v0 = make_float2(acc[mt][nt][0] + b0, acc[mt][nt][1] + b1);
            float2 v1 = make_float2(acc[mt][nt][2] + b0, acc[mt][nt][3] + b1);
            *(float2*)(out + o0 * VV + col) = v0;
            *(float2*)(out + o1 * VV + col) = v1;
        }
    }
}

// ------------------------- launch -----------------------------------------------
extern "C" void kernel_launch(void* const* d_in, const int* in_sizes, int n_in,
                              void* d_out, int out_size)
{
    const int*   tokens = (const int*)  d_in[0];
    const float* emb    = (const float*)d_in[1];
    const float* W1     = (const float*)d_in[2];
    const float* U1     = (const float*)d_in[3];
    const float* b1     = (const float*)d_in[4];
    const float* W2     = (const float*)d_in[5];
    const float* U2     = (const float*)d_in[6];
    const float* b2     = (const float*)d_in[7];
    const float* Wd     = (const float*)d_in[8];
    const float* bd     = (const float*)d_in[9];
    float* out = (float*)d_out;

    cudaFuncSetAttribute(dense_kernel, cudaFuncAttributeMaxDynamicSharedMemorySize,
                         (int)(3 * DSTG));
    cudaFuncSetAttribute(lstm_tc_kernel, cudaFuncAttributeMaxDynamicSharedMemorySize,
                         LSTM_SMEM);

    // 1) fused prep: xw1 GEMM (+barrier counter reset) + Wd transpose + U^T fp16
    prep_kernel<<<512 + 16000 + 3072, 256>>>(emb, W1, b1, tokens, Wd, U1, W2, U2);
    // 2) fused dual-layer LSTM on tensor cores (64 CTAs); layer 2 writes fp16 g_a_h
    lstm_tc_kernel<<<NCTA, 512, LSTM_SMEM>>>(b2);
    // 3) logits = h2 @ Wd + bd on HMMA tensor cores (fp16 single pass)
    dense_kernel<<<dim3(VV / 128, MROWS / 128), 256, 3 * DSTG>>>(bd, out);
}